// round 1
// baseline (speedup 1.0000x reference)
#include <cuda_runtime.h>
#include <math.h>

// ---------------- problem constants ----------------
#define B_    32768
#define DNA_  768
#define IMG_  512
#define F_    256
#define QKV3_ 768
#define DH_   744
#define GEN_  372
#define RED_  128
#define GEMB_ 64
#define SDH_  64
#define MAXSP_ 23
#define SPEC_ 1050

// ---------------- scratch (device globals; no runtime allocation) ----------------
__device__ float g_seqproj[2u * B_ * F_];     // [B,2,256]  (row b: tok0 @ b*512, tok1 @ b*512+256)
__device__ float g_qkv[2u * B_ * QKV3_];      // [B,2,768]
__device__ float g_ctx[(size_t)B_ * F_];      // 0.5*(ctx0+ctx1)
__device__ float g_t1[(size_t)B_ * F_];       // fused_pre (ctxmean @ W_o + b_o)
__device__ float g_t2[(size_t)B_ * F_];       // relu(fused_pre @ W_f1 + b_f1)
__device__ float g_h[(size_t)B_ * DH_];       // sigmoid(fused @ W_d1 + b_d1)
__device__ float g_glp[(size_t)B_ * GEN_];    // genus pre-softmax logits
__device__ float g_gemb[(size_t)B_ * GEMB_];  // genus_logits @ W_ge + b_ge

// ---------------- generic tiled SGEMM: C[M,N] = act(A[M,K] @ W[K,N] + bias) ----------------
// BM=128, BN=128, BK=16, 256 threads, 8x8 per thread.
// Requirements honored by all call sites: M % 128 == 0, K % 4 == 0, N % 4 == 0, lda/ldc % 4 == 0.
// act: 0 = none, 1 = relu, 2 = sigmoid
__global__ __launch_bounds__(256)
void sgemm_k(const float* __restrict__ A, int lda,
             const float* __restrict__ W,
             const float* __restrict__ bias,
             float* __restrict__ C, int ldc,
             int N, int K, int act)
{
    __shared__ float As[16][128];
    __shared__ float Bs[16][128];

    const int tid = threadIdx.x;
    const int tx = tid & 15;          // 0..15  (column group)
    const int ty = tid >> 4;          // 0..15  (row group)
    const long bm0 = (long)blockIdx.y * 128;
    const int  bn0 = blockIdx.x * 128;

    const int a_m = tid >> 2;         // 0..63
    const int a_k = (tid & 3) << 2;   // 0,4,8,12
    const int w_k = tid >> 5;         // 0..7
    const int w_n = (tid & 31) << 2;  // 0..124

    float acc[8][8];
#pragma unroll
    for (int i = 0; i < 8; i++)
#pragma unroll
        for (int j = 0; j < 8; j++) acc[i][j] = 0.f;

    for (int k0 = 0; k0 < K; k0 += 16) {
        // load A tile (BMxBK), transposed into As[k][m]
#pragma unroll
        for (int i = 0; i < 2; i++) {
            int m = a_m + 64 * i;
            float4 v = make_float4(0.f, 0.f, 0.f, 0.f);
            if (k0 + a_k < K)  // K % 4 == 0 -> whole float4 valid whenever first lane valid
                v = *reinterpret_cast<const float4*>(A + (bm0 + m) * (long)lda + k0 + a_k);
            As[a_k + 0][m] = v.x; As[a_k + 1][m] = v.y;
            As[a_k + 2][m] = v.z; As[a_k + 3][m] = v.w;
        }
        // load W tile (BKxBN) into Bs[k][n]
#pragma unroll
        for (int i = 0; i < 2; i++) {
            int k = w_k + 8 * i;
            float4 v = make_float4(0.f, 0.f, 0.f, 0.f);
            if (k0 + k < K && bn0 + w_n < N)  // N % 4 == 0 -> same rule
                v = *reinterpret_cast<const float4*>(W + (long)(k0 + k) * N + bn0 + w_n);
            Bs[k][w_n + 0] = v.x; Bs[k][w_n + 1] = v.y;
            Bs[k][w_n + 2] = v.z; Bs[k][w_n + 3] = v.w;
        }
        __syncthreads();

#pragma unroll
        for (int kk = 0; kk < 16; kk++) {
            float4 a0 = *reinterpret_cast<const float4*>(&As[kk][ty * 8]);
            float4 a1 = *reinterpret_cast<const float4*>(&As[kk][ty * 8 + 4]);
            float4 b0 = *reinterpret_cast<const float4*>(&Bs[kk][tx * 8]);
            float4 b1 = *reinterpret_cast<const float4*>(&Bs[kk][tx * 8 + 4]);
            float ra[8] = {a0.x, a0.y, a0.z, a0.w, a1.x, a1.y, a1.z, a1.w};
            float rb[8] = {b0.x, b0.y, b0.z, b0.w, b1.x, b1.y, b1.z, b1.w};
#pragma unroll
            for (int i = 0; i < 8; i++)
#pragma unroll
                for (int j = 0; j < 8; j++)
                    acc[i][j] = fmaf(ra[i], rb[j], acc[i][j]);
        }
        __syncthreads();
    }

    // epilogue: bias + activation + store (N predicated; M always divisible by 128 here)
#pragma unroll
    for (int i = 0; i < 8; i++) {
        long m = bm0 + ty * 8 + i;
#pragma unroll
        for (int j = 0; j < 8; j++) {
            int n = bn0 + tx * 8 + j;
            if (n < N) {
                float c = acc[i][j] + bias[n];
                if (act == 1) c = fmaxf(c, 0.f);
                else if (act == 2) c = 1.f / (1.f + expf(-c));
                C[m * (long)ldc + n] = c;
            }
        }
    }
}

static inline void gemm(const float* A, int lda, const float* W, const float* bias,
                        float* C, int ldc, int M, int N, int K, int act)
{
    dim3 grid((N + 127) / 128, M / 128);
    sgemm_k<<<grid, 256>>>(A, lda, W, bias, C, ldc, N, K, act);
}

// ---------------- attention over 2 tokens, 4 heads of dim 64 ----------------
// one warp per (row, head); lane handles dims (lane, lane+32)
// out: g_ctx[b, h*64+d] = 0.5*(ctx0[d] + ctx1[d])   (mean folded in before W_o)
__global__ void attn_k(const float* __restrict__ qkv, float* __restrict__ ctx)
{
    int gw = (blockIdx.x * blockDim.x + threadIdx.x) >> 5;
    int lane = threadIdx.x & 31;
    int b = gw >> 2, h = gw & 3;

    const float* p0 = qkv + (size_t)b * 1536 + h * 64;
    const float* p1 = p0 + 768;
    float q0a = p0[lane],       q0b = p0[32 + lane];
    float k0a = p0[256 + lane], k0b = p0[288 + lane];
    float v0a = p0[512 + lane], v0b = p0[544 + lane];
    float q1a = p1[lane],       q1b = p1[32 + lane];
    float k1a = p1[256 + lane], k1b = p1[288 + lane];
    float v1a = p1[512 + lane], v1b = p1[544 + lane];

    float s00 = q0a * k0a + q0b * k0b;
    float s01 = q0a * k1a + q0b * k1b;
    float s10 = q1a * k0a + q1b * k0b;
    float s11 = q1a * k1a + q1b * k1b;
#pragma unroll
    for (int off = 16; off; off >>= 1) {
        s00 += __shfl_xor_sync(0xffffffffu, s00, off);
        s01 += __shfl_xor_sync(0xffffffffu, s01, off);
        s10 += __shfl_xor_sync(0xffffffffu, s10, off);
        s11 += __shfl_xor_sync(0xffffffffu, s11, off);
    }
    const float sc = 0.125f;  // 1/sqrt(64)
    s00 *= sc; s01 *= sc; s10 *= sc; s11 *= sc;

    float m0 = fmaxf(s00, s01);
    float e00 = expf(s00 - m0), e01 = expf(s01 - m0);
    float r0 = 1.f / (e00 + e01);
    float a00 = e00 * r0, a01 = e01 * r0;

    float m1 = fmaxf(s10, s11);
    float e10 = expf(s10 - m1), e11 = expf(s11 - m1);
    float r1 = 1.f / (e10 + e11);
    float a10 = e10 * r1, a11 = e11 * r1;

    float oa = 0.5f * ((a00 * v0a + a01 * v1a) + (a10 * v0a + a11 * v1a));
    float ob = 0.5f * ((a00 * v0b + a01 * v1b) + (a10 * v0b + a11 * v1b));

    float* o = ctx + (size_t)b * 256 + h * 64;
    o[lane] = oa;
    o[32 + lane] = ob;
}

// ---------------- softmax over 372 (one warp per row) ----------------
__global__ void softmax372_k(const float* __restrict__ in, float* __restrict__ out)
{
    int lane = threadIdx.x & 31;
    int row = blockIdx.x * 8 + (threadIdx.x >> 5);
    const float* x = in + (size_t)row * GEN_;
    float* y = out + (size_t)row * GEN_;

    float m = -1e30f;
    for (int i = lane; i < GEN_; i += 32) m = fmaxf(m, x[i]);
#pragma unroll
    for (int off = 16; off; off >>= 1) m = fmaxf(m, __shfl_xor_sync(0xffffffffu, m, off));

    float s = 0.f;
    for (int i = lane; i < GEN_; i += 32) { float e = expf(x[i] - m); y[i] = e; s += e; }
#pragma unroll
    for (int off = 16; off; off >>= 1) s += __shfl_xor_sync(0xffffffffu, s, off);

    float inv = 1.f / s;
    for (int i = lane; i < GEN_; i += 32) y[i] *= inv;
}

// ---------------- species head: concat(gemb[64], red[128]) -> sigmoid(@W_s1+b) -> @W_s2+b ----------------
// one warp per row (grid-stride); per-warp smem row buffer: [0..191] inputs, [192..255] hidden
__global__ void spec_head_k(const float* __restrict__ gemb, const float* __restrict__ red,
                            const float* __restrict__ Ws1, const float* __restrict__ bs1,
                            const float* __restrict__ Ws2, const float* __restrict__ bs2,
                            float* __restrict__ out_loc)
{
    __shared__ float sh[8][256];
    int lane = threadIdx.x & 31;
    int w = threadIdx.x >> 5;
    float* in = sh[w];
    int gw = blockIdx.x * 8 + w;
    int nw = gridDim.x * 8;

    for (int r = gw; r < B_; r += nw) {
        in[lane]      = gemb[(size_t)r * 64 + lane];
        in[32 + lane] = gemb[(size_t)r * 64 + 32 + lane];
#pragma unroll
        for (int t = 0; t < 4; t++)
            in[64 + t * 32 + lane] = red[(size_t)r * 128 + t * 32 + lane];
        __syncwarp();
#pragma unroll
        for (int rep = 0; rep < 2; rep++) {
            int j = lane + rep * 32;
            float acc = bs1[j];
            for (int i = 0; i < 192; i++)
                acc = fmaf(in[i], Ws1[i * 64 + j], acc);
            in[192 + j] = 1.f / (1.f + expf(-acc));
        }
        __syncwarp();
        if (lane < MAXSP_) {
            float acc = bs2[lane];
#pragma unroll
            for (int j = 0; j < 64; j++)
                acc = fmaf(in[192 + j], Ws2[j * MAXSP_ + lane], acc);
            out_loc[(size_t)r * MAXSP_ + lane] = acc;
        }
        __syncwarp();
    }
}

// ---------------- species flatten: out[b,s] = genus[b,sg[s]] * local[b,sl[s]] ----------------
__global__ void flatten_k(const float* __restrict__ gen, const float* __restrict__ loc,
                          const int* __restrict__ sg, const int* __restrict__ sl,
                          float* __restrict__ out)
{
    __shared__ float g[GEN_];
    __shared__ float l[MAXSP_];
    int b = blockIdx.x;
    for (int i = threadIdx.x; i < GEN_; i += 256) g[i] = gen[(size_t)b * GEN_ + i];
    if (threadIdx.x < MAXSP_) l[threadIdx.x] = loc[(size_t)b * MAXSP_ + threadIdx.x];
    __syncthreads();
    for (int s = threadIdx.x; s < SPEC_; s += 256)
        out[(size_t)b * SPEC_ + s] = g[sg[s]] * l[sl[s]];
}

// ---------------- launch ----------------
extern "C" void kernel_launch(void* const* d_in, const int* in_sizes, int n_in,
                              void* d_out, int out_size)
{
    const float* dna   = (const float*)d_in[0];
    const float* img   = (const float*)d_in[1];
    const float* W_dna = (const float*)d_in[2];  const float* b_dna = (const float*)d_in[3];
    const float* W_img = (const float*)d_in[4];  const float* b_img = (const float*)d_in[5];
    const float* W_qkv = (const float*)d_in[6];  const float* b_qkv = (const float*)d_in[7];
    const float* W_o   = (const float*)d_in[8];  const float* b_o   = (const float*)d_in[9];
    const float* W_f1  = (const float*)d_in[10]; const float* b_f1  = (const float*)d_in[11];
    const float* W_f2  = (const float*)d_in[12]; const float* b_f2  = (const float*)d_in[13];
    const float* W_d1  = (const float*)d_in[14]; const float* b_d1  = (const float*)d_in[15];
    const float* W_d2  = (const float*)d_in[16]; const float* b_d2  = (const float*)d_in[17];
    const float* W_fp  = (const float*)d_in[18]; const float* b_fp  = (const float*)d_in[19];
    const float* W_ge  = (const float*)d_in[20]; const float* b_ge  = (const float*)d_in[21];
    const float* W_s1  = (const float*)d_in[22]; const float* b_s1  = (const float*)d_in[23];
    const float* W_s2  = (const float*)d_in[24]; const float* b_s2  = (const float*)d_in[25];
    const int*   sg    = (const int*)d_in[26];
    const int*   sl    = (const int*)d_in[27];

    float* out = (float*)d_out;
    float* o_sp  = out;                               // [B,1050]
    float* o_loc = out + (size_t)B_ * SPEC_;          // [B,23]
    float* o_gen = o_loc + (size_t)B_ * MAXSP_;       // [B,372]
    float* o_fus = o_gen + (size_t)B_ * GEN_;         // [B,256]
    float* o_red = o_fus + (size_t)B_ * F_;           // [B,128]

    float *seqproj, *qkv, *ctx, *t1, *t2, *h, *glp, *gemb;
    cudaGetSymbolAddress((void**)&seqproj, g_seqproj);
    cudaGetSymbolAddress((void**)&qkv,     g_qkv);
    cudaGetSymbolAddress((void**)&ctx,     g_ctx);
    cudaGetSymbolAddress((void**)&t1,      g_t1);
    cudaGetSymbolAddress((void**)&t2,      g_t2);
    cudaGetSymbolAddress((void**)&h,       g_h);
    cudaGetSymbolAddress((void**)&glp,     g_glp);
    cudaGetSymbolAddress((void**)&gemb,    g_gemb);

    // 1) modality projections -> seq (tok0 = dna, tok1 = img)
    gemm(dna, DNA_, W_dna, b_dna, seqproj,       2 * F_, B_, F_, DNA_, 0);
    gemm(img, IMG_, W_img, b_img, seqproj + F_,  2 * F_, B_, F_, IMG_, 0);
    // 2) qkv: view seqproj as [2B,256]
    gemm(seqproj, F_, W_qkv, b_qkv, qkv, QKV3_, 2 * B_, QKV3_, F_, 0);
    // 3) attention (mean over tokens folded in)
    attn_k<<<(B_ * 4) / 8, 256>>>(qkv, ctx);
    // 4) W_o + MLP
    gemm(ctx, F_, W_o,  b_o,  t1,    F_, B_, F_, F_, 0);
    gemm(t1,  F_, W_f1, b_f1, t2,    F_, B_, F_, F_, 1);
    gemm(t2,  F_, W_f2, b_f2, o_fus, F_, B_, F_, F_, 0);
    // 5) genus decoder
    gemm(o_fus, F_, W_d1, b_d1, h,   DH_,  B_, DH_,  F_,  2);
    gemm(h,   DH_,  W_d2, b_d2, glp, GEN_, B_, GEN_, DH_, 0);
    softmax372_k<<<B_ / 8, 256>>>(glp, o_gen);
    // 6) species inputs
    gemm(o_fus, F_,  W_fp, b_fp, o_red, RED_,  B_, RED_,  F_,   0);
    gemm(o_gen, GEN_, W_ge, b_ge, gemb, GEMB_, B_, GEMB_, GEN_, 0);
    // 7) species head + flatten
    spec_head_k<<<1024, 256>>>(gemb, o_red, W_s1, b_s1, W_s2, b_s2, o_loc);
    flatten_k<<<B_, 256>>>(o_gen, o_loc, sg, sl, o_sp);
}

// round 2
// speedup vs baseline: 2.5188x; 2.5188x over previous
#include <cuda_runtime.h>
#include <math.h>
#include <stdint.h>

// ---------------- problem constants ----------------
#define B_    32768
#define DNA_  768
#define IMG_  512
#define F_    256
#define QKV3_ 768
#define DH_   744
#define GEN_  372
#define RED_  128
#define GEMB_ 64
#define SDH_  64
#define MAXSP_ 23
#define SPEC_ 1050

// ---------------- scratch (device globals; no runtime allocation) ----------------
__device__ float g_seqproj[2u * B_ * F_];     // [B,2,256]
__device__ float g_qkv[2u * B_ * QKV3_];      // [B,2,768]
__device__ float g_ctx[(size_t)B_ * F_];      // 0.5*(ctx0+ctx1)
__device__ float g_t1[(size_t)B_ * F_];
__device__ float g_t2[(size_t)B_ * F_];
__device__ float g_h[(size_t)B_ * DH_];
__device__ float g_glp[(size_t)B_ * GEN_];
__device__ float g_gemb[(size_t)B_ * GEMB_];

// ---------------- tf32 helpers ----------------
__device__ __forceinline__ float f2tf32(float x) {
    uint32_t u;
    asm("cvt.rna.tf32.f32 %0, %1;" : "=r"(u) : "f"(x));
    return __uint_as_float(u);
}

__device__ __forceinline__ void mma_tf32(float c[4],
                                         uint32_t a0, uint32_t a1, uint32_t a2, uint32_t a3,
                                         uint32_t b0, uint32_t b1)
{
    asm volatile(
        "mma.sync.aligned.m16n8k8.row.col.f32.tf32.tf32.f32 "
        "{%0,%1,%2,%3}, {%4,%5,%6,%7}, {%8,%9}, {%0,%1,%2,%3};"
        : "+f"(c[0]), "+f"(c[1]), "+f"(c[2]), "+f"(c[3])
        : "r"(a0), "r"(a1), "r"(a2), "r"(a3), "r"(b0), "r"(b1));
}

// ---------------- tf32 tensor-core GEMM: C[M,N] = act(A[M,K] @ W[K,N] + bias) ----------------
// BM=128, BN=128, BK=16, 256 threads (8 warps, 2x4), warp tile 64x32 (4x4 m16n8k8).
// Call-site invariants: M % 128 == 0, K % 4 == 0, N % 4 == 0 (N even needed for float2 epilogue).
// act: 0 = none, 1 = relu, 2 = sigmoid
#define ASTRIDE 20    // As[m][k]: bank-conflict-free frag loads (20*gid + tig distinct mod 32)
#define BSTRIDE 136   // Bs[k][n]: 8*tig + gid distinct mod 32

__global__ __launch_bounds__(256, 2)
void mma_gemm_k(const float* __restrict__ A, int lda,
                const float* __restrict__ W,
                const float* __restrict__ bias,
                float* __restrict__ C, int ldc,
                int N, int K, int act)
{
    __shared__ float As[128 * ASTRIDE];   // 10240 B
    __shared__ float Bs[16 * BSTRIDE];    // 8704 B

    const int tid  = threadIdx.x;
    const int wid  = tid >> 5;
    const int lane = tid & 31;
    const int gid  = lane >> 2;   // 0..7
    const int tig  = lane & 3;    // 0..3

    const long bm0 = (long)blockIdx.y * 128;
    const int  bn0 = blockIdx.x * 128;

    const int warp_m = (wid & 1) * 64;   // 0 or 64
    const int warp_n = (wid >> 1) * 32;  // 0,32,64,96

    // G2S indices
    const int a_m = tid >> 2;          // 0..63 (+64)
    const int a_k = (tid & 3) << 2;    // 0,4,8,12
    const int b_k = tid >> 5;          // 0..7 (+8)
    const int b_n = (tid & 31) << 2;   // 0..124

    float c[4][4][4];
#pragma unroll
    for (int mt = 0; mt < 4; mt++)
#pragma unroll
        for (int nt = 0; nt < 4; nt++)
#pragma unroll
            for (int r = 0; r < 4; r++) c[mt][nt][r] = 0.f;

    for (int k0 = 0; k0 < K; k0 += 16) {
        // ---- A tile: [128 x 16] into As[m][k], converted to tf32 ----
#pragma unroll
        for (int i = 0; i < 2; i++) {
            int m = a_m + 64 * i;
            float4 v = make_float4(0.f, 0.f, 0.f, 0.f);
            if (k0 + a_k < K)   // K % 4 == 0 -> whole float4 valid
                v = *reinterpret_cast<const float4*>(A + (bm0 + m) * (long)lda + k0 + a_k);
            float* p = &As[m * ASTRIDE + a_k];
            p[0] = f2tf32(v.x); p[1] = f2tf32(v.y);
            p[2] = f2tf32(v.z); p[3] = f2tf32(v.w);
        }
        // ---- B tile: [16 x 128] into Bs[k][n], converted to tf32 ----
#pragma unroll
        for (int i = 0; i < 2; i++) {
            int k = b_k + 8 * i;
            float4 v = make_float4(0.f, 0.f, 0.f, 0.f);
            if (k0 + k < K && bn0 + b_n < N)   // N % 4 == 0
                v = *reinterpret_cast<const float4*>(W + (long)(k0 + k) * N + bn0 + b_n);
            float* p = &Bs[k * BSTRIDE + b_n];
            p[0] = f2tf32(v.x); p[1] = f2tf32(v.y);
            p[2] = f2tf32(v.z); p[3] = f2tf32(v.w);
        }
        __syncthreads();

#pragma unroll
        for (int ks = 0; ks < 2; ks++) {
            const int kb = ks * 8;
            uint32_t af[4][4];
#pragma unroll
            for (int mt = 0; mt < 4; mt++) {
                int r = warp_m + mt * 16;
                af[mt][0] = __float_as_uint(As[(r + gid)     * ASTRIDE + kb + tig]);
                af[mt][1] = __float_as_uint(As[(r + gid + 8) * ASTRIDE + kb + tig]);
                af[mt][2] = __float_as_uint(As[(r + gid)     * ASTRIDE + kb + tig + 4]);
                af[mt][3] = __float_as_uint(As[(r + gid + 8) * ASTRIDE + kb + tig + 4]);
            }
            uint32_t bf[4][2];
#pragma unroll
            for (int nt = 0; nt < 4; nt++) {
                int n = warp_n + nt * 8;
                bf[nt][0] = __float_as_uint(Bs[(kb + tig)     * BSTRIDE + n + gid]);
                bf[nt][1] = __float_as_uint(Bs[(kb + tig + 4) * BSTRIDE + n + gid]);
            }
#pragma unroll
            for (int mt = 0; mt < 4; mt++)
#pragma unroll
                for (int nt = 0; nt < 4; nt++)
                    mma_tf32(c[mt][nt], af[mt][0], af[mt][1], af[mt][2], af[mt][3],
                             bf[nt][0], bf[nt][1]);
        }
        __syncthreads();
    }

    // ---- epilogue: bias + activation + float2 stores ----
#pragma unroll
    for (int mt = 0; mt < 4; mt++) {
        long r0 = bm0 + warp_m + mt * 16 + gid;
#pragma unroll
        for (int nt = 0; nt < 4; nt++) {
            int col = bn0 + warp_n + nt * 8 + tig * 2;
            if (col < N) {   // N even, col even -> col+1 < N too
                float2 bv = *reinterpret_cast<const float2*>(bias + col);
                float x0 = c[mt][nt][0] + bv.x;
                float x1 = c[mt][nt][1] + bv.y;
                float x2 = c[mt][nt][2] + bv.x;
                float x3 = c[mt][nt][3] + bv.y;
                if (act == 1) {
                    x0 = fmaxf(x0, 0.f); x1 = fmaxf(x1, 0.f);
                    x2 = fmaxf(x2, 0.f); x3 = fmaxf(x3, 0.f);
                } else if (act == 2) {
                    x0 = 1.f / (1.f + expf(-x0)); x1 = 1.f / (1.f + expf(-x1));
                    x2 = 1.f / (1.f + expf(-x2)); x3 = 1.f / (1.f + expf(-x3));
                }
                *reinterpret_cast<float2*>(C + r0 * (long)ldc + col)       = make_float2(x0, x1);
                *reinterpret_cast<float2*>(C + (r0 + 8) * (long)ldc + col) = make_float2(x2, x3);
            }
        }
    }
}

static inline void gemm(const float* A, int lda, const float* W, const float* bias,
                        float* C, int ldc, int M, int N, int K, int act)
{
    dim3 grid((N + 127) / 128, M / 128);
    mma_gemm_k<<<grid, 256>>>(A, lda, W, bias, C, ldc, N, K, act);
}

// ---------------- attention over 2 tokens, 4 heads of dim 64 ----------------
__global__ void attn_k(const float* __restrict__ qkv, float* __restrict__ ctx)
{
    int gw = (blockIdx.x * blockDim.x + threadIdx.x) >> 5;
    int lane = threadIdx.x & 31;
    int b = gw >> 2, h = gw & 3;

    const float* p0 = qkv + (size_t)b * 1536 + h * 64;
    const float* p1 = p0 + 768;
    float q0a = p0[lane],       q0b = p0[32 + lane];
    float k0a = p0[256 + lane], k0b = p0[288 + lane];
    float v0a = p0[512 + lane], v0b = p0[544 + lane];
    float q1a = p1[lane],       q1b = p1[32 + lane];
    float k1a = p1[256 + lane], k1b = p1[288 + lane];
    float v1a = p1[512 + lane], v1b = p1[544 + lane];

    float s00 = q0a * k0a + q0b * k0b;
    float s01 = q0a * k1a + q0b * k1b;
    float s10 = q1a * k0a + q1b * k0b;
    float s11 = q1a * k1a + q1b * k1b;
#pragma unroll
    for (int off = 16; off; off >>= 1) {
        s00 += __shfl_xor_sync(0xffffffffu, s00, off);
        s01 += __shfl_xor_sync(0xffffffffu, s01, off);
        s10 += __shfl_xor_sync(0xffffffffu, s10, off);
        s11 += __shfl_xor_sync(0xffffffffu, s11, off);
    }
    const float sc = 0.125f;
    s00 *= sc; s01 *= sc; s10 *= sc; s11 *= sc;

    float m0 = fmaxf(s00, s01);
    float e00 = expf(s00 - m0), e01 = expf(s01 - m0);
    float r0 = 1.f / (e00 + e01);
    float a00 = e00 * r0, a01 = e01 * r0;

    float m1 = fmaxf(s10, s11);
    float e10 = expf(s10 - m1), e11 = expf(s11 - m1);
    float r1 = 1.f / (e10 + e11);
    float a10 = e10 * r1, a11 = e11 * r1;

    float oa = 0.5f * ((a00 * v0a + a01 * v1a) + (a10 * v0a + a11 * v1a));
    float ob = 0.5f * ((a00 * v0b + a01 * v1b) + (a10 * v0b + a11 * v1b));

    float* o = ctx + (size_t)b * 256 + h * 64;
    o[lane] = oa;
    o[32 + lane] = ob;
}

// ---------------- softmax over 372 (one warp per row) ----------------
__global__ void softmax372_k(const float* __restrict__ in, float* __restrict__ out)
{
    int lane = threadIdx.x & 31;
    int row = blockIdx.x * 8 + (threadIdx.x >> 5);
    const float* x = in + (size_t)row * GEN_;
    float* y = out + (size_t)row * GEN_;

    float m = -1e30f;
    for (int i = lane; i < GEN_; i += 32) m = fmaxf(m, x[i]);
#pragma unroll
    for (int off = 16; off; off >>= 1) m = fmaxf(m, __shfl_xor_sync(0xffffffffu, m, off));

    float s = 0.f;
    for (int i = lane; i < GEN_; i += 32) { float e = expf(x[i] - m); y[i] = e; s += e; }
#pragma unroll
    for (int off = 16; off; off >>= 1) s += __shfl_xor_sync(0xffffffffu, s, off);

    float inv = 1.f / s;
    for (int i = lane; i < GEN_; i += 32) y[i] *= inv;
}

// ---------------- species head ----------------
__global__ void spec_head_k(const float* __restrict__ gemb, const float* __restrict__ red,
                            const float* __restrict__ Ws1, const float* __restrict__ bs1,
                            const float* __restrict__ Ws2, const float* __restrict__ bs2,
                            float* __restrict__ out_loc)
{
    __shared__ float sh[8][256];
    int lane = threadIdx.x & 31;
    int w = threadIdx.x >> 5;
    float* in = sh[w];
    int gw = blockIdx.x * 8 + w;
    int nw = gridDim.x * 8;

    for (int r = gw; r < B_; r += nw) {
        in[lane]      = gemb[(size_t)r * 64 + lane];
        in[32 + lane] = gemb[(size_t)r * 64 + 32 + lane];
#pragma unroll
        for (int t = 0; t < 4; t++)
            in[64 + t * 32 + lane] = red[(size_t)r * 128 + t * 32 + lane];
        __syncwarp();
#pragma unroll
        for (int rep = 0; rep < 2; rep++) {
            int j = lane + rep * 32;
            float acc = bs1[j];
            for (int i = 0; i < 192; i++)
                acc = fmaf(in[i], Ws1[i * 64 + j], acc);
            in[192 + j] = 1.f / (1.f + expf(-acc));
        }
        __syncwarp();
        if (lane < MAXSP_) {
            float acc = bs2[lane];
#pragma unroll
            for (int j = 0; j < 64; j++)
                acc = fmaf(in[192 + j], Ws2[j * MAXSP_ + lane], acc);
            out_loc[(size_t)r * MAXSP_ + lane] = acc;
        }
        __syncwarp();
    }
}

// ---------------- species flatten ----------------
__global__ void flatten_k(const float* __restrict__ gen, const float* __restrict__ loc,
                          const int* __restrict__ sg, const int* __restrict__ sl,
                          float* __restrict__ out)
{
    __shared__ float g[GEN_];
    __shared__ float l[MAXSP_];
    int b = blockIdx.x;
    for (int i = threadIdx.x; i < GEN_; i += 256) g[i] = gen[(size_t)b * GEN_ + i];
    if (threadIdx.x < MAXSP_) l[threadIdx.x] = loc[(size_t)b * MAXSP_ + threadIdx.x];
    __syncthreads();
    for (int s = threadIdx.x; s < SPEC_; s += 256)
        out[(size_t)b * SPEC_ + s] = g[sg[s]] * l[sl[s]];
}

// ---------------- launch ----------------
extern "C" void kernel_launch(void* const* d_in, const int* in_sizes, int n_in,
                              void* d_out, int out_size)
{
    const float* dna   = (const float*)d_in[0];
    const float* img   = (const float*)d_in[1];
    const float* W_dna = (const float*)d_in[2];  const float* b_dna = (const float*)d_in[3];
    const float* W_img = (const float*)d_in[4];  const float* b_img = (const float*)d_in[5];
    const float* W_qkv = (const float*)d_in[6];  const float* b_qkv = (const float*)d_in[7];
    const float* W_o   = (const float*)d_in[8];  const float* b_o   = (const float*)d_in[9];
    const float* W_f1  = (const float*)d_in[10]; const float* b_f1  = (const float*)d_in[11];
    const float* W_f2  = (const float*)d_in[12]; const float* b_f2  = (const float*)d_in[13];
    const float* W_d1  = (const float*)d_in[14]; const float* b_d1  = (const float*)d_in[15];
    const float* W_d2  = (const float*)d_in[16]; const float* b_d2  = (const float*)d_in[17];
    const float* W_fp  = (const float*)d_in[18]; const float* b_fp  = (const float*)d_in[19];
    const float* W_ge  = (const float*)d_in[20]; const float* b_ge  = (const float*)d_in[21];
    const float* W_s1  = (const float*)d_in[22]; const float* b_s1  = (const float*)d_in[23];
    const float* W_s2  = (const float*)d_in[24]; const float* b_s2  = (const float*)d_in[25];
    const int*   sg    = (const int*)d_in[26];
    const int*   sl    = (const int*)d_in[27];

    float* out = (float*)d_out;
    float* o_sp  = out;                               // [B,1050]
    float* o_loc = out + (size_t)B_ * SPEC_;          // [B,23]
    float* o_gen = o_loc + (size_t)B_ * MAXSP_;       // [B,372]
    float* o_fus = o_gen + (size_t)B_ * GEN_;         // [B,256]
    float* o_red = o_fus + (size_t)B_ * F_;           // [B,128]

    float *seqproj, *qkv, *ctx, *t1, *t2, *h, *glp, *gemb;
    cudaGetSymbolAddress((void**)&seqproj, g_seqproj);
    cudaGetSymbolAddress((void**)&qkv,     g_qkv);
    cudaGetSymbolAddress((void**)&ctx,     g_ctx);
    cudaGetSymbolAddress((void**)&t1,      g_t1);
    cudaGetSymbolAddress((void**)&t2,      g_t2);
    cudaGetSymbolAddress((void**)&h,       g_h);
    cudaGetSymbolAddress((void**)&glp,     g_glp);
    cudaGetSymbolAddress((void**)&gemb,    g_gemb);

    // 1) modality projections -> seq (tok0 = dna, tok1 = img)
    gemm(dna, DNA_, W_dna, b_dna, seqproj,       2 * F_, B_, F_, DNA_, 0);
    gemm(img, IMG_, W_img, b_img, seqproj + F_,  2 * F_, B_, F_, IMG_, 0);
    // 2) qkv: view seqproj as [2B,256]
    gemm(seqproj, F_, W_qkv, b_qkv, qkv, QKV3_, 2 * B_, QKV3_, F_, 0);
    // 3) attention (mean over tokens folded in)
    attn_k<<<(B_ * 4) / 8, 256>>>(qkv, ctx);
    // 4) W_o + MLP
    gemm(ctx, F_, W_o,  b_o,  t1,    F_, B_, F_, F_, 0);
    gemm(t1,  F_, W_f1, b_f1, t2,    F_, B_, F_, F_, 1);
    gemm(t2,  F_, W_f2, b_f2, o_fus, F_, B_, F_, F_, 0);
    // 5) genus decoder
    gemm(o_fus, F_, W_d1, b_d1, h,   DH_,  B_, DH_,  F_,  2);
    gemm(h,   DH_,  W_d2, b_d2, glp, GEN_, B_, GEN_, DH_, 0);
    softmax372_k<<<B_ / 8, 256>>>(glp, o_gen);
    // 6) species inputs
    gemm(o_fus, F_,  W_fp, b_fp, o_red, RED_,  B_, RED_,  F_,   0);
    gemm(o_gen, GEN_, W_ge, b_ge, gemb, GEMB_, B_, GEMB_, GEN_, 0);
    // 7) species head + flatten
    spec_head_k<<<1024, 256>>>(gemb, o_red, W_s1, b_s1, W_s2, b_s2, o_loc);
    flatten_k<<<B_, 256>>>(o_gen, o_loc, sg, sl, o_sp);
}

// round 3
// speedup vs baseline: 2.8723x; 1.1404x over previous
#include <cuda_runtime.h>
#include <math.h>
#include <stdint.h>

// ---------------- problem constants ----------------
#define B_    32768
#define DNA_  768
#define IMG_  512
#define F_    256
#define QKV3_ 768
#define DH_   744
#define GEN_  372
#define RED_  128
#define GEMB_ 64
#define SDH_  64
#define MAXSP_ 23
#define SPEC_ 1050

// ---------------- scratch (device globals; no runtime allocation) ----------------
__device__ float g_seqproj[2u * B_ * F_];
__device__ float g_qkv[2u * B_ * QKV3_];
__device__ float g_ctx[(size_t)B_ * F_];
__device__ float g_t1[(size_t)B_ * F_];
__device__ float g_t2[(size_t)B_ * F_];
__device__ float g_h[(size_t)B_ * DH_];
__device__ float g_glp[(size_t)B_ * GEN_];
__device__ float g_gemb[(size_t)B_ * GEMB_];

// ---------------- helpers ----------------
__device__ __forceinline__ uint32_t f2tf32u(float x) {
    uint32_t u;
    asm("cvt.rna.tf32.f32 %0, %1;" : "=r"(u) : "f"(x));
    return u;
}

__device__ __forceinline__ void mma_tf32(float c[4],
                                         uint32_t a0, uint32_t a1, uint32_t a2, uint32_t a3,
                                         uint32_t b0, uint32_t b1)
{
    asm volatile(
        "mma.sync.aligned.m16n8k8.row.col.f32.tf32.tf32.f32 "
        "{%0,%1,%2,%3}, {%4,%5,%6,%7}, {%8,%9}, {%0,%1,%2,%3};"
        : "+f"(c[0]), "+f"(c[1]), "+f"(c[2]), "+f"(c[3])
        : "r"(a0), "r"(a1), "r"(a2), "r"(a3), "r"(b0), "r"(b1));
}

// cp.async 16B with zero-fill when pred==false (cp-size 16, src-size 0 -> zfill)
__device__ __forceinline__ void cpasync16(uint32_t saddr, const float* g, bool pred) {
    int sz = pred ? 16 : 0;
    asm volatile("cp.async.cg.shared.global [%0], [%1], 16, %2;"
                 :: "r"(saddr), "l"(g), "r"(sz));
}
__device__ __forceinline__ void cp_commit() { asm volatile("cp.async.commit_group;"); }
__device__ __forceinline__ void cp_wait1()  { asm volatile("cp.async.wait_group 1;"); }

// ---------------- tf32 tensor-core GEMM, 2-stage cp.async pipeline ----------------
// BM=128, BN=128, BK=16. 128 threads (4 warps), warp tile 64x64 (4x8 m16n8k8).
// Invariants at all call sites: M % 128 == 0, K % 4 == 0, N % 4 == 0, lda >= K.
// act: 0 = none, 1 = relu, 2 = sigmoid
#define ASTRIDE 20    // As[m][k] padded row; frag pattern conflict-free
#define BSTRIDE 136   // Bs[k][n] padded row; frag pattern conflict-free

__global__ __launch_bounds__(128, 2)
void mma_gemm_k(const float* __restrict__ A, int lda,
                const float* __restrict__ W,
                const float* __restrict__ bias,
                float* __restrict__ C, int ldc,
                int N, int K, int act)
{
    __shared__ float As[2][128 * ASTRIDE];   // 2 x 10240 B
    __shared__ float Bs[2][16 * BSTRIDE];    // 2 x 8704 B

    const int tid  = threadIdx.x;
    const int wid  = tid >> 5;
    const int lane = tid & 31;
    const int gid  = lane >> 2;   // 0..7
    const int tig  = lane & 3;    // 0..3

    const long bm0 = (long)blockIdx.y * 128;
    const int  bn0 = blockIdx.x * 128;

    const int warp_m = (wid & 1) * 64;
    const int warp_n = (wid >> 1) * 64;

    // G2S mappings (128 threads)
    const int a_row = tid >> 2;          // 0..31 (+32i)
    const int a_col = (tid & 3) << 2;    // 0,4,8,12
    const int b_row = tid >> 5;          // 0..3 (+4i)
    const int b_col = (tid & 31) << 2;   // 0..124

    const int nk = (K + 15) >> 4;

    float c[4][8][4];
#pragma unroll
    for (int mt = 0; mt < 4; mt++)
#pragma unroll
        for (int nt = 0; nt < 8; nt++)
#pragma unroll
            for (int r = 0; r < 4; r++) c[mt][nt][r] = 0.f;

    // stage load
    auto load_stage = [&](int it, int st) {
        const int k0 = it << 4;
#pragma unroll
        for (int i = 0; i < 4; i++) {
            int m = a_row + 32 * i;
            uint32_t sa = (uint32_t)__cvta_generic_to_shared(&As[st][m * ASTRIDE + a_col]);
            cpasync16(sa, A + (bm0 + m) * (long)lda + k0 + a_col, (k0 + a_col) < K);
        }
#pragma unroll
        for (int i = 0; i < 4; i++) {
            int k = b_row + 4 * i;
            uint32_t sb = (uint32_t)__cvta_generic_to_shared(&Bs[st][k * BSTRIDE + b_col]);
            bool p = ((k0 + k) < K) && ((bn0 + b_col) < N);
            cpasync16(sb, W + (long)(k0 + k) * N + bn0 + b_col, p);
        }
    };

    load_stage(0, 0);
    cp_commit();

    for (int it = 0; it < nk; it++) {
        const int st = it & 1;
        if (it + 1 < nk) load_stage(it + 1, st ^ 1);
        cp_commit();
        cp_wait1();
        __syncthreads();

#pragma unroll
        for (int ks = 0; ks < 2; ks++) {
            const int kb = ks * 8;
            uint32_t af[4][4];
#pragma unroll
            for (int mt = 0; mt < 4; mt++) {
                int r = warp_m + mt * 16;
                af[mt][0] = f2tf32u(As[st][(r + gid)     * ASTRIDE + kb + tig]);
                af[mt][1] = f2tf32u(As[st][(r + gid + 8) * ASTRIDE + kb + tig]);
                af[mt][2] = f2tf32u(As[st][(r + gid)     * ASTRIDE + kb + tig + 4]);
                af[mt][3] = f2tf32u(As[st][(r + gid + 8) * ASTRIDE + kb + tig + 4]);
            }
            uint32_t bf[8][2];
#pragma unroll
            for (int nt = 0; nt < 8; nt++) {
                int n = warp_n + nt * 8 + gid;
                bf[nt][0] = f2tf32u(Bs[st][(kb + tig)     * BSTRIDE + n]);
                bf[nt][1] = f2tf32u(Bs[st][(kb + tig + 4) * BSTRIDE + n]);
            }
#pragma unroll
            for (int mt = 0; mt < 4; mt++)
#pragma unroll
                for (int nt = 0; nt < 8; nt++)
                    mma_tf32(c[mt][nt], af[mt][0], af[mt][1], af[mt][2], af[mt][3],
                             bf[nt][0], bf[nt][1]);
        }
        __syncthreads();
    }

    // ---- epilogue: bias + activation + float2 stores ----
#pragma unroll
    for (int mt = 0; mt < 4; mt++) {
        long r0 = bm0 + warp_m + mt * 16 + gid;
#pragma unroll
        for (int nt = 0; nt < 8; nt++) {
            int col = bn0 + warp_n + nt * 8 + tig * 2;
            if (col < N) {   // N even, col even -> col+1 < N too
                float2 bv = *reinterpret_cast<const float2*>(bias + col);
                float x0 = c[mt][nt][0] + bv.x;
                float x1 = c[mt][nt][1] + bv.y;
                float x2 = c[mt][nt][2] + bv.x;
                float x3 = c[mt][nt][3] + bv.y;
                if (act == 1) {
                    x0 = fmaxf(x0, 0.f); x1 = fmaxf(x1, 0.f);
                    x2 = fmaxf(x2, 0.f); x3 = fmaxf(x3, 0.f);
                } else if (act == 2) {
                    x0 = 1.f / (1.f + expf(-x0)); x1 = 1.f / (1.f + expf(-x1));
                    x2 = 1.f / (1.f + expf(-x2)); x3 = 1.f / (1.f + expf(-x3));
                }
                *reinterpret_cast<float2*>(C + r0 * (long)ldc + col)       = make_float2(x0, x1);
                *reinterpret_cast<float2*>(C + (r0 + 8) * (long)ldc + col) = make_float2(x2, x3);
            }
        }
    }
}

static inline void gemm(const float* A, int lda, const float* W, const float* bias,
                        float* C, int ldc, int M, int N, int K, int act)
{
    dim3 grid((N + 127) / 128, M / 128);
    mma_gemm_k<<<grid, 128>>>(A, lda, W, bias, C, ldc, N, K, act);
}

// ---------------- attention over 2 tokens, 4 heads of dim 64 ----------------
__global__ void attn_k(const float* __restrict__ qkv, float* __restrict__ ctx)
{
    int gw = (blockIdx.x * blockDim.x + threadIdx.x) >> 5;
    int lane = threadIdx.x & 31;
    int b = gw >> 2, h = gw & 3;

    const float* p0 = qkv + (size_t)b * 1536 + h * 64;
    const float* p1 = p0 + 768;
    float q0a = p0[lane],       q0b = p0[32 + lane];
    float k0a = p0[256 + lane], k0b = p0[288 + lane];
    float v0a = p0[512 + lane], v0b = p0[544 + lane];
    float q1a = p1[lane],       q1b = p1[32 + lane];
    float k1a = p1[256 + lane], k1b = p1[288 + lane];
    float v1a = p1[512 + lane], v1b = p1[544 + lane];

    float s00 = q0a * k0a + q0b * k0b;
    float s01 = q0a * k1a + q0b * k1b;
    float s10 = q1a * k0a + q1b * k0b;
    float s11 = q1a * k1a + q1b * k1b;
#pragma unroll
    for (int off = 16; off; off >>= 1) {
        s00 += __shfl_xor_sync(0xffffffffu, s00, off);
        s01 += __shfl_xor_sync(0xffffffffu, s01, off);
        s10 += __shfl_xor_sync(0xffffffffu, s10, off);
        s11 += __shfl_xor_sync(0xffffffffu, s11, off);
    }
    const float sc = 0.125f;
    s00 *= sc; s01 *= sc; s10 *= sc; s11 *= sc;

    float m0 = fmaxf(s00, s01);
    float e00 = expf(s00 - m0), e01 = expf(s01 - m0);
    float r0 = 1.f / (e00 + e01);
    float a00 = e00 * r0, a01 = e01 * r0;

    float m1 = fmaxf(s10, s11);
    float e10 = expf(s10 - m1), e11 = expf(s11 - m1);
    float r1 = 1.f / (e10 + e11);
    float a10 = e10 * r1, a11 = e11 * r1;

    float oa = 0.5f * ((a00 * v0a + a01 * v1a) + (a10 * v0a + a11 * v1a));
    float ob = 0.5f * ((a00 * v0b + a01 * v1b) + (a10 * v0b + a11 * v1b));

    float* o = ctx + (size_t)b * 256 + h * 64;
    o[lane] = oa;
    o[32 + lane] = ob;
}

// ---------------- softmax over 372 (one warp per row) ----------------
__global__ void softmax372_k(const float* __restrict__ in, float* __restrict__ out)
{
    int lane = threadIdx.x & 31;
    int row = blockIdx.x * 8 + (threadIdx.x >> 5);
    const float* x = in + (size_t)row * GEN_;
    float* y = out + (size_t)row * GEN_;

    float m = -1e30f;
    for (int i = lane; i < GEN_; i += 32) m = fmaxf(m, x[i]);
#pragma unroll
    for (int off = 16; off; off >>= 1) m = fmaxf(m, __shfl_xor_sync(0xffffffffu, m, off));

    float s = 0.f;
    for (int i = lane; i < GEN_; i += 32) { float e = expf(x[i] - m); y[i] = e; s += e; }
#pragma unroll
    for (int off = 16; off; off >>= 1) s += __shfl_xor_sync(0xffffffffu, s, off);

    float inv = 1.f / s;
    for (int i = lane; i < GEN_; i += 32) y[i] *= inv;
}

// ---------------- species head ----------------
__global__ void spec_head_k(const float* __restrict__ gemb, const float* __restrict__ red,
                            const float* __restrict__ Ws1, const float* __restrict__ bs1,
                            const float* __restrict__ Ws2, const float* __restrict__ bs2,
                            float* __restrict__ out_loc)
{
    __shared__ float sh[8][256];
    int lane = threadIdx.x & 31;
    int w = threadIdx.x >> 5;
    float* in = sh[w];
    int gw = blockIdx.x * 8 + w;
    int nw = gridDim.x * 8;

    for (int r = gw; r < B_; r += nw) {
        in[lane]      = gemb[(size_t)r * 64 + lane];
        in[32 + lane] = gemb[(size_t)r * 64 + 32 + lane];
#pragma unroll
        for (int t = 0; t < 4; t++)
            in[64 + t * 32 + lane] = red[(size_t)r * 128 + t * 32 + lane];
        __syncwarp();
#pragma unroll
        for (int rep = 0; rep < 2; rep++) {
            int j = lane + rep * 32;
            float acc = bs1[j];
            for (int i = 0; i < 192; i++)
                acc = fmaf(in[i], Ws1[i * 64 + j], acc);
            in[192 + j] = 1.f / (1.f + expf(-acc));
        }
        __syncwarp();
        if (lane < MAXSP_) {
            float acc = bs2[lane];
#pragma unroll
            for (int j = 0; j < 64; j++)
                acc = fmaf(in[192 + j], Ws2[j * MAXSP_ + lane], acc);
            out_loc[(size_t)r * MAXSP_ + lane] = acc;
        }
        __syncwarp();
    }
}

// ---------------- species flatten ----------------
__global__ void flatten_k(const float* __restrict__ gen, const float* __restrict__ loc,
                          const int* __restrict__ sg, const int* __restrict__ sl,
                          float* __restrict__ out)
{
    __shared__ float g[GEN_];
    __shared__ float l[MAXSP_];
    int b = blockIdx.x;
    for (int i = threadIdx.x; i < GEN_; i += 256) g[i] = gen[(size_t)b * GEN_ + i];
    if (threadIdx.x < MAXSP_) l[threadIdx.x] = loc[(size_t)b * MAXSP_ + threadIdx.x];
    __syncthreads();
    for (int s = threadIdx.x; s < SPEC_; s += 256)
        out[(size_t)b * SPEC_ + s] = g[sg[s]] * l[sl[s]];
}

// ---------------- launch ----------------
extern "C" void kernel_launch(void* const* d_in, const int* in_sizes, int n_in,
                              void* d_out, int out_size)
{
    const float* dna   = (const float*)d_in[0];
    const float* img   = (const float*)d_in[1];
    const float* W_dna = (const float*)d_in[2];  const float* b_dna = (const float*)d_in[3];
    const float* W_img = (const float*)d_in[4];  const float* b_img = (const float*)d_in[5];
    const float* W_qkv = (const float*)d_in[6];  const float* b_qkv = (const float*)d_in[7];
    const float* W_o   = (const float*)d_in[8];  const float* b_o   = (const float*)d_in[9];
    const float* W_f1  = (const float*)d_in[10]; const float* b_f1  = (const float*)d_in[11];
    const float* W_f2  = (const float*)d_in[12]; const float* b_f2  = (const float*)d_in[13];
    const float* W_d1  = (const float*)d_in[14]; const float* b_d1  = (const float*)d_in[15];
    const float* W_d2  = (const float*)d_in[16]; const float* b_d2  = (const float*)d_in[17];
    const float* W_fp  = (const float*)d_in[18]; const float* b_fp  = (const float*)d_in[19];
    const float* W_ge  = (const float*)d_in[20]; const float* b_ge  = (const float*)d_in[21];
    const float* W_s1  = (const float*)d_in[22]; const float* b_s1  = (const float*)d_in[23];
    const float* W_s2  = (const float*)d_in[24]; const float* b_s2  = (const float*)d_in[25];
    const int*   sg    = (const int*)d_in[26];
    const int*   sl    = (const int*)d_in[27];

    float* out = (float*)d_out;
    float* o_sp  = out;
    float* o_loc = out + (size_t)B_ * SPEC_;
    float* o_gen = o_loc + (size_t)B_ * MAXSP_;
    float* o_fus = o_gen + (size_t)B_ * GEN_;
    float* o_red = o_fus + (size_t)B_ * F_;

    float *seqproj, *qkv, *ctx, *t1, *t2, *h, *glp, *gemb;
    cudaGetSymbolAddress((void**)&seqproj, g_seqproj);
    cudaGetSymbolAddress((void**)&qkv,     g_qkv);
    cudaGetSymbolAddress((void**)&ctx,     g_ctx);
    cudaGetSymbolAddress((void**)&t1,      g_t1);
    cudaGetSymbolAddress((void**)&t2,      g_t2);
    cudaGetSymbolAddress((void**)&h,       g_h);
    cudaGetSymbolAddress((void**)&glp,     g_glp);
    cudaGetSymbolAddress((void**)&gemb,    g_gemb);

    gemm(dna, DNA_, W_dna, b_dna, seqproj,       2 * F_, B_, F_, DNA_, 0);
    gemm(img, IMG_, W_img, b_img, seqproj + F_,  2 * F_, B_, F_, IMG_, 0);
    gemm(seqproj, F_, W_qkv, b_qkv, qkv, QKV3_, 2 * B_, QKV3_, F_, 0);
    attn_k<<<(B_ * 4) / 8, 256>>>(qkv, ctx);
    gemm(ctx, F_, W_o,  b_o,  t1,    F_, B_, F_, F_, 0);
    gemm(t1,  F_, W_f1, b_f1, t2,    F_, B_, F_, F_, 1);
    gemm(t2,  F_, W_f2, b_f2, o_fus, F_, B_, F_, F_, 0);
    gemm(o_fus, F_, W_d1, b_d1, h,   DH_,  B_, DH_,  F_,  2);
    gemm(h,   DH_,  W_d2, b_d2, glp, GEN_, B_, GEN_, DH_, 0);
    softmax372_k<<<B_ / 8, 256>>>(glp, o_gen);
    gemm(o_fus, F_,  W_fp, b_fp, o_red, RED_,  B_, RED_,  F_,   0);
    gemm(o_gen, GEN_, W_ge, b_ge, gemb, GEMB_, B_, GEMB_, GEN_, 0);
    spec_head_k<<<1024, 256>>>(gemb, o_red, W_s1, b_s1, W_s2, b_s2, o_loc);
    flatten_k<<<B_, 256>>>(o_gen, o_loc, sg, sl, o_sp);
}

// round 11
// speedup vs baseline: 3.5143x; 1.2235x over previous
#include <cuda_runtime.h>
#include <cuda_fp16.h>
#include <math.h>
#include <stdint.h>

// ---------------- problem constants ----------------
#define B_    32768
#define DNA_  768
#define IMG_  512
#define F_    256
#define QKV3_ 768
#define DH_   744
#define GEN_  372
#define RED_  128
#define GEMB_ 64
#define MAXSP_ 23
#define SPEC_ 1050

// ---------------- scratch (device globals; no runtime allocation) ----------------
__device__ __align__(16) float g_seqproj[2u * B_ * F_];
__device__ __align__(16) float g_qkv[2u * B_ * QKV3_];
__device__ __align__(16) float g_ctx[(size_t)B_ * F_];
__device__ __align__(16) float g_t1[(size_t)B_ * F_];
__device__ __align__(16) float g_t2[(size_t)B_ * F_];
__device__ __align__(16) float g_h[(size_t)B_ * DH_];
__device__ __align__(16) float g_glp[(size_t)B_ * GEN_];
__device__ __align__(16) float g_gemb[(size_t)B_ * GEMB_];

// transposed fp16 weights: [Npad, Kpad], zero padded. offsets in elements:
#define OFF_DNA 0u          // Np 256, Kp 768
#define OFF_IMG 196608u     // Np 256, Kp 512
#define OFF_QKV 327680u     // Np 768, Kp 256
#define OFF_O   524288u     // Np 256, Kp 256
#define OFF_F1  589824u
#define OFF_F2  655360u
#define OFF_D1  720896u     // Np 768 (744), Kp 256
#define OFF_D2  917504u     // Np 384 (372), Kp 768 (744)
#define OFF_FP  1212416u    // Np 128, Kp 256
#define OFF_GE  1245184u    // Np 128 (64), Kp 384 (372)
#define WT_TOTAL 1294336u
__device__ __align__(16) __half g_wT[WT_TOTAL];

// ---------------- mma / cp.async helpers ----------------
__device__ __forceinline__ void mma_f16(float c[4], const uint32_t a[4], const uint32_t b[2]) {
    asm volatile(
        "mma.sync.aligned.m16n8k16.row.col.f32.f16.f16.f32 "
        "{%0,%1,%2,%3}, {%4,%5,%6,%7}, {%8,%9}, {%0,%1,%2,%3};"
        : "+f"(c[0]), "+f"(c[1]), "+f"(c[2]), "+f"(c[3])
        : "r"(a[0]), "r"(a[1]), "r"(a[2]), "r"(a[3]), "r"(b[0]), "r"(b[1]));
}
__device__ __forceinline__ void cpasync16(uint32_t saddr, const void* g) {
    asm volatile("cp.async.ca.shared.global [%0], [%1], 16;" :: "r"(saddr), "l"(g));
}
__device__ __forceinline__ void cp_commit() { asm volatile("cp.async.commit_group;"); }
__device__ __forceinline__ void cp_wait0()  { asm volatile("cp.async.wait_group 0;"); }

// ---------------- weight prepass: W[K,N] fp32 -> Wt[Np,Kp] fp16 (transposed, padded) ----
__global__ void prep_w_k(const float* __restrict__ W, int K, int N,
                         __half* __restrict__ Wt, int Kp, int Np)
{
    int idx = blockIdx.x * 256 + threadIdx.x;
    if (idx >= Np * Kp) return;
    int n = idx / Kp, k = idx - n * Kp;
    float v = (n < N && k < K) ? W[(size_t)k * N + n] : 0.f;
    Wt[idx] = __float2half(v);
}

// ---------------- fp16 m16n8k16 GEMM: C[M,N] = act(A[M,K] @ W[K,N] + bias) --------
// Wt = W^T fp16 [Npad, Kpad]. BM=128, BN=128, BK=32. 128 threads (4 warps @ 64x64).
// Invariants: M % 128 == 0, K % 4 == 0, N even, lda % 4 == 0, Kpad >= 32*ceil(K/32),
// Npad >= 128*ceil(N/128).
// act: 0 none, 1 relu, 2 sigmoid
#define AST 40   // halfs per smem row (20 words) -> conflict-free fragment loads

__global__ __launch_bounds__(128, 2)
void hgemm_k(const float* __restrict__ A, int lda,
             const __half* __restrict__ Bt, int Kp,
             const float* __restrict__ bias,
             float* __restrict__ C, int ldc,
             int N, int K, int act)
{
    __shared__ __align__(16) __half As[2][128 * AST];
    __shared__ __align__(16) __half Bs[2][128 * AST];

    const int tid  = threadIdx.x;
    const int wid  = tid >> 5;
    const int lane = tid & 31;
    const int gid  = lane >> 2;   // 0..7
    const int tig  = lane & 3;    // 0..3

    const long bm0 = (long)blockIdx.y * 128;
    const int  bn0 = blockIdx.x * 128;
    const int  warp_m = (wid & 1) * 64;
    const int  warp_n = (wid >> 1) * 64;
    const int  ns = (K + 31) >> 5;

    const float*  Ab = A + bm0 * (long)lda;
    const __half* Bb = Bt + (long)bn0 * Kp;

    float c[4][8][4];
#pragma unroll
    for (int mt = 0; mt < 4; mt++)
#pragma unroll
        for (int nt = 0; nt < 8; nt++)
#pragma unroll
            for (int r = 0; r < 4; r++) c[mt][nt][r] = 0.f;

    uint32_t abuf[16];

    // A: 128x32 fp32 -> fp16; idx = i*128+tid: row = idx>>3, kq = (idx&7)*4
    auto ldgA = [&](int s) {
        const int k0 = s << 5;
#pragma unroll
        for (int i = 0; i < 8; i++) {
            int idx = i * 128 + tid;
            int row = idx >> 3;
            int kq  = (idx & 7) << 2;
            float4 v = make_float4(0.f, 0.f, 0.f, 0.f);
            if (k0 + kq < K)                 // K % 4 == 0 -> whole float4 valid
                v = *reinterpret_cast<const float4*>(Ab + (long)row * lda + k0 + kq);
            __half2 h0 = __floats2half2_rn(v.x, v.y);
            __half2 h1 = __floats2half2_rn(v.z, v.w);
            abuf[2 * i]     = *reinterpret_cast<uint32_t*>(&h0);
            abuf[2 * i + 1] = *reinterpret_cast<uint32_t*>(&h1);
        }
    };
    auto stsA = [&](int b) {
#pragma unroll
        for (int i = 0; i < 8; i++) {
            int idx = i * 128 + tid;
            int row = idx >> 3;
            int kq  = (idx & 7) << 2;
            *reinterpret_cast<uint2*>(&As[b][row * AST + kq]) =
                make_uint2(abuf[2 * i], abuf[2 * i + 1]);
        }
    };
    // W: 128 rows x 32 halfs via cp.async 16B; idx = i*128+tid: n = idx>>2, kq = (idx&3)*8
    auto cpW = [&](int s, int b) {
        const int k0 = s << 5;
#pragma unroll
        for (int i = 0; i < 4; i++) {
            int idx = i * 128 + tid;
            int n  = idx >> 2;
            int kq = (idx & 3) << 3;
            uint32_t dst = (uint32_t)__cvta_generic_to_shared(&Bs[b][n * AST + kq]);
            cpasync16(dst, Bb + (long)n * Kp + k0 + kq);   // padded: always in-bounds
        }
    };

    auto compute = [&](int b) {
        const uint32_t* Aw = reinterpret_cast<const uint32_t*>(As[b]);
        const uint32_t* Bw = reinterpret_cast<const uint32_t*>(Bs[b]);
#pragma unroll
        for (int ks = 0; ks < 2; ks++) {
            const int kw = ks * 8;          // k16 step = 8 words
            uint32_t af[4][4];
#pragma unroll
            for (int mt = 0; mt < 4; mt++) {
                int r = warp_m + mt * 16 + gid;
                af[mt][0] = Aw[r * 20 + kw + tig];
                af[mt][1] = Aw[(r + 8) * 20 + kw + tig];
                af[mt][2] = Aw[r * 20 + kw + tig + 4];
                af[mt][3] = Aw[(r + 8) * 20 + kw + tig + 4];
            }
            uint32_t bf[8][2];
#pragma unroll
            for (int nt = 0; nt < 8; nt++) {
                int n = warp_n + nt * 8 + gid;
                bf[nt][0] = Bw[n * 20 + kw + tig];
                bf[nt][1] = Bw[n * 20 + kw + tig + 4];
            }
#pragma unroll
            for (int mt = 0; mt < 4; mt++)
#pragma unroll
                for (int nt = 0; nt < 8; nt++)
                    mma_f16(c[mt][nt], af[mt], bf[nt]);
        }
    };

    // prologue
    ldgA(0); stsA(0);
    cpW(0, 0); cp_commit();

    for (int s = 0; s < ns; s++) {
        const int cb = s & 1, nb = cb ^ 1;
        cp_wait0();            // W(s) landed (single pending group)
        __syncthreads();       // As(s)/Bs(s) visible; all warps done with stage s-1
        if (s + 1 < ns) {
            ldgA(s + 1);
            cpW(s + 1, nb); cp_commit();
        }
        compute(cb);
        if (s + 1 < ns) stsA(nb);
    }

    // ---- epilogue: bias + activation + float2 stores ----
#pragma unroll
    for (int mt = 0; mt < 4; mt++) {
        long r0 = bm0 + warp_m + mt * 16 + gid;
#pragma unroll
        for (int nt = 0; nt < 8; nt++) {
            int col = bn0 + warp_n + nt * 8 + tig * 2;
            if (col < N) {   // N even -> col+1 < N too
                float2 bv = *reinterpret_cast<const float2*>(bias + col);
                float x0 = c[mt][nt][0] + bv.x;
                float x1 = c[mt][nt][1] + bv.y;
                float x2 = c[mt][nt][2] + bv.x;
                float x3 = c[mt][nt][3] + bv.y;
                if (act == 1) {
                    x0 = fmaxf(x0, 0.f); x1 = fmaxf(x1, 0.f);
                    x2 = fmaxf(x2, 0.f); x3 = fmaxf(x3, 0.f);
                } else if (act == 2) {
                    x0 = 1.f / (1.f + expf(-x0)); x1 = 1.f / (1.f + expf(-x1));
                    x2 = 1.f / (1.f + expf(-x2)); x3 = 1.f / (1.f + expf(-x3));
                }
                *reinterpret_cast<float2*>(C + r0 * (long)ldc + col)       = make_float2(x0, x1);
                *reinterpret_cast<float2*>(C + (r0 + 8) * (long)ldc + col) = make_float2(x2, x3);
            }
        }
    }
}

// ---------------- attention over 2 tokens, 4 heads of dim 64 ----------------
__global__ void attn_k(const float* __restrict__ qkv, float* __restrict__ ctx)
{
    int gw = (blockIdx.x * blockDim.x + threadIdx.x) >> 5;
    int lane = threadIdx.x & 31;
    int b = gw >> 2, h = gw & 3;

    const float* p0 = qkv + (size_t)b * 1536 + h * 64;
    const float* p1 = p0 + 768;
    float q0a = p0[lane],       q0b = p0[32 + lane];
    float k0a = p0[256 + lane], k0b = p0[288 + lane];
    float v0a = p0[512 + lane], v0b = p0[544 + lane];
    float q1a = p1[lane],       q1b = p1[32 + lane];
    float k1a = p1[256 + lane], k1b = p1[288 + lane];
    float v1a = p1[512 + lane], v1b = p1[544 + lane];

    float s00 = q0a * k0a + q0b * k0b;
    float s01 = q0a * k1a + q0b * k1b;
    float s10 = q1a * k0a + q1b * k0b;
    float s11 = q1a * k1a + q1b * k1b;
#pragma unroll
    for (int off = 16; off; off >>= 1) {
        s00 += __shfl_xor_sync(0xffffffffu, s00, off);
        s01 += __shfl_xor_sync(0xffffffffu, s01, off);
        s10 += __shfl_xor_sync(0xffffffffu, s10, off);
        s11 += __shfl_xor_sync(0xffffffffu, s11, off);
    }
    const float sc = 0.125f;
    s00 *= sc; s01 *= sc; s10 *= sc; s11 *= sc;

    float m0 = fmaxf(s00, s01);
    float e00 = expf(s00 - m0), e01 = expf(s01 - m0);
    float r0 = 1.f / (e00 + e01);
    float a00 = e00 * r0, a01 = e01 * r0;

    float m1 = fmaxf(s10, s11);
    float e10 = expf(s10 - m1), e11 = expf(s11 - m1);
    float r1 = 1.f / (e10 + e11);
    float a10 = e10 * r1, a11 = e11 * r1;

    float oa = 0.5f * ((a00 * v0a + a01 * v1a) + (a10 * v0a + a11 * v1a));
    float ob = 0.5f * ((a00 * v0b + a01 * v1b) + (a10 * v0b + a11 * v1b));

    float* o = ctx + (size_t)b * 256 + h * 64;
    o[lane] = oa;
    o[32 + lane] = ob;
}

// ---------------- softmax over 372 (one warp per row) ----------------
__global__ void softmax372_k(const float* __restrict__ in, float* __restrict__ out)
{
    int lane = threadIdx.x & 31;
    int row = blockIdx.x * 8 + (threadIdx.x >> 5);
    const float* x = in + (size_t)row * GEN_;
    float* y = out + (size_t)row * GEN_;

    float m = -1e30f;
    for (int i = lane; i < GEN_; i += 32) m = fmaxf(m, x[i]);
#pragma unroll
    for (int off = 16; off; off >>= 1) m = fmaxf(m, __shfl_xor_sync(0xffffffffu, m, off));

    float s = 0.f;
    for (int i = lane; i < GEN_; i += 32) { float e = expf(x[i] - m); y[i] = e; s += e; }
#pragma unroll
    for (int off = 16; off; off >>= 1) s += __shfl_xor_sync(0xffffffffu, s, off);

    float inv = 1.f / s;
    for (int i = lane; i < GEN_; i += 32) y[i] *= inv;
}

// ---------------- species head ----------------
__global__ void spec_head_k(const float* __restrict__ gemb, const float* __restrict__ red,
                            const float* __restrict__ Ws1, const float* __restrict__ bs1,
                            const float* __restrict__ Ws2, const float* __restrict__ bs2,
                            float* __restrict__ out_loc)
{
    __shared__ float sh[8][256];
    int lane = threadIdx.x & 31;
    int w = threadIdx.x >> 5;
    float* in = sh[w];
    int gw = blockIdx.x * 8 + w;
    int nw = gridDim.x * 8;

    for (int r = gw; r < B_; r += nw) {
        in[lane]      = gemb[(size_t)r * 64 + lane];
        in[32 + lane] = gemb[(size_t)r * 64 + 32 + lane];
#pragma unroll
        for (int t = 0; t < 4; t++)
            in[64 + t * 32 + lane] = red[(size_t)r * 128 + t * 32 + lane];
        __syncwarp();
#pragma unroll
        for (int rep = 0; rep < 2; rep++) {
            int j = lane + rep * 32;
            float acc = bs1[j];
            for (int i = 0; i < 192; i++)
                acc = fmaf(in[i], Ws1[i * 64 + j], acc);
            in[192 + j] = 1.f / (1.f + expf(-acc));
        }
        __syncwarp();
        if (lane < MAXSP_) {
            float acc = bs2[lane];
#pragma unroll
            for (int j = 0; j < 64; j++)
                acc = fmaf(in[192 + j], Ws2[j * MAXSP_ + lane], acc);
            out_loc[(size_t)r * MAXSP_ + lane] = acc;
        }
        __syncwarp();
    }
}

// ---------------- species flatten ----------------
__global__ void flatten_k(const float* __restrict__ gen, const float* __restrict__ loc,
                          const int* __restrict__ sg, const int* __restrict__ sl,
                          float* __restrict__ out)
{
    __shared__ float g[GEN_];
    __shared__ float l[MAXSP_];
    int b = blockIdx.x;
    for (int i = threadIdx.x; i < GEN_; i += 256) g[i] = gen[(size_t)b * GEN_ + i];
    if (threadIdx.x < MAXSP_) l[threadIdx.x] = loc[(size_t)b * MAXSP_ + threadIdx.x];
    __syncthreads();
    for (int s = threadIdx.x; s < SPEC_; s += 256)
        out[(size_t)b * SPEC_ + s] = g[sg[s]] * l[sl[s]];
}

// ---------------- host side ----------------
static void prep(const float* W, int K, int N, __half* Wt, int Kp, int Np)
{
    int tot = Np * Kp;
    prep_w_k<<<(tot + 255) / 256, 256>>>(W, K, N, Wt, Kp, Np);
}

static void hgemm(const float* A, int lda, const __half* wt, int Kp,
                  const float* bias, float* C, int ldc, long M, int N, int K, int act)
{
    dim3 g((unsigned)((N + 127) / 128), (unsigned)(M / 128));
    hgemm_k<<<g, 128>>>(A, lda, wt, Kp, bias, C, ldc, N, K, act);
}

extern "C" void kernel_launch(void* const* d_in, const int* in_sizes, int n_in,
                              void* d_out, int out_size)
{
    const float* dna   = (const float*)d_in[0];
    const float* img   = (const float*)d_in[1];
    const float* W_dna = (const float*)d_in[2];  const float* b_dna = (const float*)d_in[3];
    const float* W_img = (const float*)d_in[4];  const float* b_img = (const float*)d_in[5];
    const float* W_qkv = (const float*)d_in[6];  const float* b_qkv = (const float*)d_in[7];
    const float* W_o   = (const float*)d_in[8];  const float* b_o   = (const float*)d_in[9];
    const float* W_f1  = (const float*)d_in[10]; const float* b_f1  = (const float*)d_in[11];
    const float* W_f2  = (const float*)d_in[12]; const float* b_f2  = (const float*)d_in[13];
    const float* W_d1  = (const float*)d_in[14]; const float* b_d1  = (const float*)d_in[15];
    const float* W_d2  = (const float*)d_in[16]; const float* b_d2  = (const float*)d_in[17];
    const float* W_fp  = (const float*)d_in[18]; const float* b_fp  = (const float*)d_in[19];
    const float* W_ge  = (const float*)d_in[20]; const float* b_ge  = (const float*)d_in[21];
    const float* W_s1  = (const float*)d_in[22]; const float* b_s1  = (const float*)d_in[23];
    const float* W_s2  = (const float*)d_in[24]; const float* b_s2  = (const float*)d_in[25];
    const int*   sg    = (const int*)d_in[26];
    const int*   sl    = (const int*)d_in[27];

    float* out = (float*)d_out;
    float* o_sp  = out;
    float* o_loc = out + (size_t)B_ * SPEC_;
    float* o_gen = o_loc + (size_t)B_ * MAXSP_;
    float* o_fus = o_gen + (size_t)B_ * GEN_;
    float* o_red = o_fus + (size_t)B_ * F_;

    float *seqproj, *qkv, *ctx, *t1, *t2, *h, *glp, *gemb;
    cudaGetSymbolAddress((void**)&seqproj, g_seqproj);
    cudaGetSymbolAddress((void**)&qkv,     g_qkv);
    cudaGetSymbolAddress((void**)&ctx,     g_ctx);
    cudaGetSymbolAddress((void**)&t1,      g_t1);
    cudaGetSymbolAddress((void**)&t2,      g_t2);
    cudaGetSymbolAddress((void**)&h,       g_h);
    cudaGetSymbolAddress((void**)&glp,     g_glp);
    cudaGetSymbolAddress((void**)&gemb,    g_gemb);
    __half* wt;
    cudaGetSymbolAddress((void**)&wt, g_wT);

    // ---- weight prepass (transpose + fp16, zero-padded) ----
    prep(W_dna, DNA_, F_,    wt + OFF_DNA, 768, 256);
    prep(W_img, IMG_, F_,    wt + OFF_IMG, 512, 256);
    prep(W_qkv, F_,   QKV3_, wt + OFF_QKV, 256, 768);
    prep(W_o,   F_,   F_,    wt + OFF_O,   256, 256);
    prep(W_f1,  F_,   F_,    wt + OFF_F1,  256, 256);
    prep(W_f2,  F_,   F_,    wt + OFF_F2,  256, 256);
    prep(W_d1,  F_,   DH_,   wt + OFF_D1,  256, 768);
    prep(W_d2,  DH_,  GEN_,  wt + OFF_D2,  768, 384);
    prep(W_fp,  F_,   RED_,  wt + OFF_FP,  256, 128);
    prep(W_ge,  GEN_, GEMB_, wt + OFF_GE,  384, 128);

    // ---- forward ----
    hgemm(dna, DNA_, wt + OFF_DNA, 768, b_dna, seqproj,      2 * F_, B_, F_, DNA_, 0);
    hgemm(img, IMG_, wt + OFF_IMG, 512, b_img, seqproj + F_, 2 * F_, B_, F_, IMG_, 0);
    hgemm(seqproj, F_, wt + OFF_QKV, 256, b_qkv, qkv, QKV3_, 2L * B_, QKV3_, F_, 0);
    attn_k<<<(B_ * 4) / 8, 256>>>(qkv, ctx);
    hgemm(ctx, F_, wt + OFF_O,  256, b_o,  t1,    F_, B_, F_, F_, 0);
    hgemm(t1,  F_, wt + OFF_F1, 256, b_f1, t2,    F_, B_, F_, F_, 1);
    hgemm(t2,  F_, wt + OFF_F2, 256, b_f2, o_fus, F_, B_, F_, F_, 0);
    hgemm(o_fus, F_, wt + OFF_D1, 256, b_d1, h,   DH_,  B_, DH_,  F_,  2);
    hgemm(h, DH_,    wt + OFF_D2, 768, b_d2, glp, GEN_, B_, GEN_, DH_, 0);
    softmax372_k<<<B_ / 8, 256>>>(glp, o_gen);
    hgemm(o_fus, F_,  wt + OFF_FP, 256, b_fp, o_red, RED_,  B_, RED_,  F_,  0);
    hgemm(o_gen, GEN_, wt + OFF_GE, 384, b_ge, gemb, GEMB_, B_, GEMB_, GEN_, 0);
    spec_head_k<<<1024, 256>>>(gemb, o_red, W_s1, b_s1, W_s2, b_s2, o_loc);
    flatten_k<<<B_, 256>>>(o_gen, o_loc, sg, sl, o_sp);
}

// round 16
// speedup vs baseline: 3.5569x; 1.0121x over previous
#include <cuda_runtime.h>
#include <cuda_fp16.h>
#include <math.h>
#include <stdint.h>

// ---------------- problem constants ----------------
#define B_    32768
#define DNA_  768
#define IMG_  512
#define F_    256
#define QKV3_ 768
#define DH_   744
#define GEN_  372
#define RED_  128
#define GEMB_ 64
#define MAXSP_ 23
#define SPEC_ 1050

// ---------------- scratch (device globals; no runtime allocation) ----------------
__device__ __align__(16) float g_seqproj[2u * B_ * F_];
__device__ __align__(16) float g_qkv[2u * B_ * QKV3_];
__device__ __align__(16) float g_ctx[(size_t)B_ * F_];
__device__ __align__(16) float g_t1[(size_t)B_ * F_];
__device__ __align__(16) float g_t2[(size_t)B_ * F_];
__device__ __align__(16) float g_h[(size_t)B_ * DH_];
__device__ __align__(16) float g_glp[(size_t)B_ * GEN_];
__device__ __align__(16) float g_gemb[(size_t)B_ * GEMB_];

// fp16 W^T in fragment-ordered 128x32 tile blobs (4096 halfs per tile), zero padded.
#define OFF_DNA 0u
#define OFF_IMG 196608u
#define OFF_QKV 327680u
#define OFF_O   524288u
#define OFF_F1  589824u
#define OFF_F2  655360u
#define OFF_D1  720896u
#define OFF_D2  917504u
#define OFF_FP  1212416u
#define OFF_GE  1245184u
#define WT_TOTAL 1294336u
__device__ __align__(16) __half g_wT[WT_TOTAL];

// ---------------- mma / cp.async helpers ----------------
__device__ __forceinline__ void mma_f16(float c[4], const uint32_t a[4], const uint32_t b0,
                                        const uint32_t b1) {
    asm volatile(
        "mma.sync.aligned.m16n8k16.row.col.f32.f16.f16.f32 "
        "{%0,%1,%2,%3}, {%4,%5,%6,%7}, {%8,%9}, {%0,%1,%2,%3};"
        : "+f"(c[0]), "+f"(c[1]), "+f"(c[2]), "+f"(c[3])
        : "r"(a[0]), "r"(a[1]), "r"(a[2]), "r"(a[3]), "r"(b0), "r"(b1));
}
__device__ __forceinline__ void cpasync16(uint32_t saddr, const void* g) {
    asm volatile("cp.async.ca.shared.global [%0], [%1], 16;" :: "r"(saddr), "l"(g));
}
__device__ __forceinline__ void cp_commit() { asm volatile("cp.async.commit_group;"); }
__device__ __forceinline__ void cp_wait0()  { asm volatile("cp.async.wait_group 0;"); }

// ---------------- merged weight prepass -> fragment-ordered tiles ----------------
// Tile blob layout (words of 2 halfs; 2048 words = 4096 halfs per 128n x 32k tile):
//   word = (((wb*2 + ks)*4 + np)*32 + gid*4 + tig)*4 + (j23*2 + j01)
//   where n_in_tile = wb*64 + np*16 + j23*8 + gid, k_in_tile = ks*16 + j01*8 + tig*2 + h
struct PA   { const float* W; int K, N, Kp, Np; unsigned off; };
struct PA10 { PA a[10]; };

__global__ void prep_all_k(PA10 p, __half* __restrict__ Wt)
{
    PA a = p.a[blockIdx.y];
    int idx = blockIdx.x * 256 + threadIdx.x;
    if (idx >= a.Np * a.Kp) return;
    int n = idx / a.Kp, k = idx - n * a.Kp;
    float v = (n < a.N && k < a.K) ? a.W[(size_t)k * a.N + n] : 0.f;

    int tbn = n >> 7, tbk = k >> 5;
    int nn = n & 127, kk = k & 31;
    int wb  = nn >> 6,        np  = (nn >> 4) & 3;
    int j23 = (nn >> 3) & 1,  gid = nn & 7;
    int ks  = kk >> 4,        j01 = (kk >> 3) & 1;
    int tig = (kk & 7) >> 1,  h   = kk & 1;
    int word = (((wb * 2 + ks) * 4 + np) * 32 + gid * 4 + tig) * 4 + (j23 * 2 + j01);
    size_t hidx = ((size_t)(tbn * (a.Kp >> 5) + tbk)) * 4096 + (size_t)word * 2 + h;
    Wt[a.off + hidx] = __float2half(v);
}

// ---------------- fp16 m16n8k16 GEMM, fragment-ordered smem ----------------
// C[M,N] = act(A[M,K] @ W[K,N] + bias). BM=128, BN=128, BK=32; 128 thr (4 warps @ 64x64).
__global__ __launch_bounds__(128, 2)
void hgemm_k(const float* __restrict__ A, int lda,
             const __half* __restrict__ Bt, int Kp,
             const float* __restrict__ bias,
             float* __restrict__ C, int ldc,
             int N, int K, int act)
{
    __shared__ __align__(16) uint4 AsQ[2][512];   // 8KB per stage, fragment order
    __shared__ __align__(16) uint4 BsQ[2][512];

    const int tid  = threadIdx.x;
    const int wid  = tid >> 5;
    const int lane = tid & 31;
    const int gid  = lane >> 2;
    const int tig  = lane & 3;

    const long bm0 = (long)blockIdx.y * 128;
    const int  bn0 = blockIdx.x * 128;
    const int  warp_m = (wid & 1) * 64;
    const int  warp_n = (wid >> 1) * 64;
    const int  mb = wid & 1;
    const int  wb = wid >> 1;
    const int  ns = (K + 31) >> 5;

    const float*  Ab = A + bm0 * (long)lda;
    const __half* Bb = Bt + (size_t)blockIdx.x * (size_t)(Kp >> 5) * 4096;

    float c[4][8][4];
#pragma unroll
    for (int mt = 0; mt < 4; mt++)
#pragma unroll
        for (int nt = 0; nt < 8; nt++)
#pragma unroll
            for (int r = 0; r < 4; r++) c[mt][nt][r] = 0.f;

    uint32_t abuf[16];

    auto ldgA = [&](int s) {
        const int k0 = s << 5;
#pragma unroll
        for (int i = 0; i < 8; i++) {
            int idx = i * 128 + tid;
            int row = idx >> 3;
            int kq  = (idx & 7) << 2;
            float4 v = make_float4(0.f, 0.f, 0.f, 0.f);
            if (k0 + kq < K)
                v = *reinterpret_cast<const float4*>(Ab + (long)row * lda + k0 + kq);
            __half2 h0 = __floats2half2_rn(v.x, v.y);
            __half2 h1 = __floats2half2_rn(v.z, v.w);
            abuf[2 * i]     = *reinterpret_cast<uint32_t*>(&h0);
            abuf[2 * i + 1] = *reinterpret_cast<uint32_t*>(&h1);
        }
    };
    auto stsA = [&](int b) {
        uint32_t* Aw = reinterpret_cast<uint32_t*>(AsQ[b]);
#pragma unroll
        for (int i = 0; i < 8; i++) {
            int idx = i * 128 + tid;
            int row = idx >> 3;
            int w0  = (idx & 7) << 1;
            int mbb = row >> 6, mt = (row >> 4) & 3, hi = (row >> 3) & 1, g = row & 7;
#pragma unroll
            for (int t = 0; t < 2; t++) {
                int w = w0 + t;
                int ks = w >> 3, kk = (w >> 2) & 1, tg = w & 3;
                int word = (((mbb * 2 + ks) * 4 + mt) * 32 + g * 4 + tg) * 4 + kk * 2 + hi;
                Aw[word] = abuf[2 * i + t];
            }
        }
    };
    auto cpW = [&](int s, int b) {
        const __half* src = Bb + (size_t)s * 4096;
#pragma unroll
        for (int i = 0; i < 4; i++) {
            int e = i * 128 + tid;
            uint32_t dst = (uint32_t)__cvta_generic_to_shared(&BsQ[b][e]);
            cpasync16(dst, src + (size_t)e * 8);
        }
    };

    auto compute = [&](int b) {
        const uint4* A4 = AsQ[b];
        const uint4* B4 = BsQ[b];
#pragma unroll
        for (int ks = 0; ks < 2; ks++) {
            uint4 af[4];
#pragma unroll
            for (int mt = 0; mt < 4; mt++)
                af[mt] = A4[((mb * 2 + ks) * 4 + mt) * 32 + lane];
            uint4 bf[4];
#pragma unroll
            for (int np = 0; np < 4; np++)
                bf[np] = B4[((wb * 2 + ks) * 4 + np) * 32 + lane];
#pragma unroll
            for (int mt = 0; mt < 4; mt++)
#pragma unroll
                for (int np = 0; np < 4; np++) {
                    const uint32_t* a = reinterpret_cast<const uint32_t*>(&af[mt]);
                    mma_f16(c[mt][2 * np],     a, bf[np].x, bf[np].y);
                    mma_f16(c[mt][2 * np + 1], a, bf[np].z, bf[np].w);
                }
        }
    };

    ldgA(0); stsA(0);
    cpW(0, 0); cp_commit();

    for (int s = 0; s < ns; s++) {
        const int cb = s & 1, nb = cb ^ 1;
        cp_wait0();
        __syncthreads();
        if (s + 1 < ns) {
            ldgA(s + 1);
            cpW(s + 1, nb); cp_commit();
        }
        compute(cb);
        if (s + 1 < ns) stsA(nb);
    }

    // ---- epilogue: bias + activation + float2 stores ----
#pragma unroll
    for (int mt = 0; mt < 4; mt++) {
        long r0 = bm0 + warp_m + mt * 16 + gid;
#pragma unroll
        for (int nt = 0; nt < 8; nt++) {
            int col = bn0 + warp_n + nt * 8 + tig * 2;
            if (col < N) {
                float2 bv = *reinterpret_cast<const float2*>(bias + col);
                float x0 = c[mt][nt][0] + bv.x;
                float x1 = c[mt][nt][1] + bv.y;
                float x2 = c[mt][nt][2] + bv.x;
                float x3 = c[mt][nt][3] + bv.y;
                if (act == 1) {
                    x0 = fmaxf(x0, 0.f); x1 = fmaxf(x1, 0.f);
                    x2 = fmaxf(x2, 0.f); x3 = fmaxf(x3, 0.f);
                } else if (act == 2) {
                    x0 = 1.f / (1.f + expf(-x0)); x1 = 1.f / (1.f + expf(-x1));
                    x2 = 1.f / (1.f + expf(-x2)); x3 = 1.f / (1.f + expf(-x3));
                }
                *reinterpret_cast<float2*>(C + r0 * (long)ldc + col)       = make_float2(x0, x1);
                *reinterpret_cast<float2*>(C + (r0 + 8) * (long)ldc + col) = make_float2(x2, x3);
            }
        }
    }
}

// ---------------- attention over 2 tokens, 4 heads of dim 64 ----------------
__global__ void attn_k(const float* __restrict__ qkv, float* __restrict__ ctx)
{
    int gw = (blockIdx.x * blockDim.x + threadIdx.x) >> 5;
    int lane = threadIdx.x & 31;
    int b = gw >> 2, h = gw & 3;

    const float* p0 = qkv + (size_t)b * 1536 + h * 64;
    const float* p1 = p0 + 768;
    float q0a = p0[lane],       q0b = p0[32 + lane];
    float k0a = p0[256 + lane], k0b = p0[288 + lane];
    float v0a = p0[512 + lane], v0b = p0[544 + lane];
    float q1a = p1[lane],       q1b = p1[32 + lane];
    float k1a = p1[256 + lane], k1b = p1[288 + lane];
    float v1a = p1[512 + lane], v1b = p1[544 + lane];

    float s00 = q0a * k0a + q0b * k0b;
    float s01 = q0a * k1a + q0b * k1b;
    float s10 = q1a * k0a + q1b * k0b;
    float s11 = q1a * k1a + q1b * k1b;
#pragma unroll
    for (int off = 16; off; off >>= 1) {
        s00 += __shfl_xor_sync(0xffffffffu, s00, off);
        s01 += __shfl_xor_sync(0xffffffffu, s01, off);
        s10 += __shfl_xor_sync(0xffffffffu, s10, off);
        s11 += __shfl_xor_sync(0xffffffffu, s11, off);
    }
    const float sc = 0.125f;
    s00 *= sc; s01 *= sc; s10 *= sc; s11 *= sc;

    float m0 = fmaxf(s00, s01);
    float e00 = expf(s00 - m0), e01 = expf(s01 - m0);
    float r0 = 1.f / (e00 + e01);
    float a00 = e00 * r0, a01 = e01 * r0;

    float m1 = fmaxf(s10, s11);
    float e10 = expf(s10 - m1), e11 = expf(s11 - m1);
    float r1 = 1.f / (e10 + e11);
    float a10 = e10 * r1, a11 = e11 * r1;

    float oa = 0.5f * ((a00 * v0a + a01 * v1a) + (a10 * v0a + a11 * v1a));
    float ob = 0.5f * ((a00 * v0b + a01 * v1b) + (a10 * v0b + a11 * v1b));

    float* o = ctx + (size_t)b * 256 + h * 64;
    o[lane] = oa;
    o[32 + lane] = ob;
}

// ---------------- softmax over 372 (one warp per row) ----------------
__global__ void softmax372_k(const float* __restrict__ in, float* __restrict__ out)
{
    int lane = threadIdx.x & 31;
    int row = blockIdx.x * 8 + (threadIdx.x >> 5);
    const float* x = in + (size_t)row * GEN_;
    float* y = out + (size_t)row * GEN_;

    float m = -1e30f;
    for (int i = lane; i < GEN_; i += 32) m = fmaxf(m, x[i]);
#pragma unroll
    for (int off = 16; off; off >>= 1) m = fmaxf(m, __shfl_xor_sync(0xffffffffu, m, off));

    float s = 0.f;
    for (int i = lane; i < GEN_; i += 32) { float e = expf(x[i] - m); y[i] = e; s += e; }
#pragma unroll
    for (int off = 16; off; off >>= 1) s += __shfl_xor_sync(0xffffffffu, s, off);

    float inv = 1.f / s;
    for (int i = lane; i < GEN_; i += 32) y[i] *= inv;
}

// ---------------- species head ----------------
__global__ void spec_head_k(const float* __restrict__ gemb, const float* __restrict__ red,
                            const float* __restrict__ Ws1, const float* __restrict__ bs1,
                            const float* __restrict__ Ws2, const float* __restrict__ bs2,
                            float* __restrict__ out_loc)
{
    __shared__ float sh[8][256];
    int lane = threadIdx.x & 31;
    int w = threadIdx.x >> 5;
    float* in = sh[w];
    int gw = blockIdx.x * 8 + w;
    int nw = gridDim.x * 8;

    for (int r = gw; r < B_; r += nw) {
        in[lane]      = gemb[(size_t)r * 64 + lane];
        in[32 + lane] = gemb[(size_t)r * 64 + 32 + lane];
#pragma unroll
        for (int t = 0; t < 4; t++)
            in[64 + t * 32 + lane] = red[(size_t)r * 128 + t * 32 + lane];
        __syncwarp();
#pragma unroll
        for (int rep = 0; rep < 2; rep++) {
            int j = lane + rep * 32;
            float acc = bs1[j];
            for (int i = 0; i < 192; i++)
                acc = fmaf(in[i], Ws1[i * 64 + j], acc);
            in[192 + j] = 1.f / (1.f + expf(-acc));
        }
        __syncwarp();
        if (lane < MAXSP_) {
            float acc = bs2[lane];
#pragma unroll
            for (int j = 0; j < 64; j++)
                acc = fmaf(in[192 + j], Ws2[j * MAXSP_ + lane], acc);
            out_loc[(size_t)r * MAXSP_ + lane] = acc;
        }
        __syncwarp();
    }
}

// ---------------- species flatten ----------------
__global__ void flatten_k(const float* __restrict__ gen, const float* __restrict__ loc,
                          const int* __restrict__ sg, const int* __restrict__ sl,
                          float* __restrict__ out)
{
    __shared__ float g[GEN_];
    __shared__ float l[MAXSP_];
    int b = blockIdx.x;
    for (int i = threadIdx.x; i < GEN_; i += 256) g[i] = gen[(size_t)b * GEN_ + i];
    if (threadIdx.x < MAXSP_) l[threadIdx.x] = loc[(size_t)b * MAXSP_ + threadIdx.x];
    __syncthreads();
    for (int s = threadIdx.x; s < SPEC_; s += 256)
        out[(size_t)b * SPEC_ + s] = g[sg[s]] * l[sl[s]];
}

// ---------------- host side ----------------
static void hgemm(const float* A, int lda, const __half* wt, int Kp,
                  const float* bias, float* C, int ldc, long M, int N, int K, int act)
{
    dim3 g((unsigned)((N + 127) / 128), (unsigned)(M / 128));
    hgemm_k<<<g, 128>>>(A, lda, wt, Kp, bias, C, ldc, N, K, act);
}

extern "C" void kernel_launch(void* const* d_in, const int* in_sizes, int n_in,
                              void* d_out, int out_size)
{
    const float* dna   = (const float*)d_in[0];
    const float* img   = (const float*)d_in[1];
    const float* W_dna = (const float*)d_in[2];  const float* b_dna = (const float*)d_in[3];
    const float* W_img = (const float*)d_in[4];  const float* b_img = (const float*)d_in[5];
    const float* W_qkv = (const float*)d_in[6];  const float* b_qkv = (const float*)d_in[7];
    const float* W_o   = (const float*)d_in[8];  const float* b_o   = (const float*)d_in[9];
    const float* W_f1  = (const float*)d_in[10]; const float* b_f1  = (const float*)d_in[11];
    const float* W_f2  = (const float*)d_in[12]; const float* b_f2  = (const float*)d_in[13];
    const float* W_d1  = (const float*)d_in[14]; const float* b_d1  = (const float*)d_in[15];
    const float* W_d2  = (const float*)d_in[16]; const float* b_d2  = (const float*)d_in[17];
    const float* W_fp  = (const float*)d_in[18]; const float* b_fp  = (const float*)d_in[19];
    const float* W_ge  = (const float*)d_in[20]; const float* b_ge  = (const float*)d_in[21];
    const float* W_s1  = (const float*)d_in[22]; const float* b_s1  = (const float*)d_in[23];
    const float* W_s2  = (const float*)d_in[24]; const float* b_s2  = (const float*)d_in[25];
    const int*   sg    = (const int*)d_in[26];
    const int*   sl    = (const int*)d_in[27];

    float* out = (float*)d_out;
    float* o_sp  = out;
    float* o_loc = out + (size_t)B_ * SPEC_;
    float* o_gen = o_loc + (size_t)B_ * MAXSP_;
    float* o_fus = o_gen + (size_t)B_ * GEN_;
    float* o_red = o_fus + (size_t)B_ * F_;

    float *seqproj, *qkv, *ctx, *t1, *t2, *h, *glp, *gemb;
    cudaGetSymbolAddress((void**)&seqproj, g_seqproj);
    cudaGetSymbolAddress((void**)&qkv,     g_qkv);
    cudaGetSymbolAddress((void**)&ctx,     g_ctx);
    cudaGetSymbolAddress((void**)&t1,      g_t1);
    cudaGetSymbolAddress((void**)&t2,      g_t2);
    cudaGetSymbolAddress((void**)&h,       g_h);
    cudaGetSymbolAddress((void**)&glp,     g_glp);
    cudaGetSymbolAddress((void**)&gemb,    g_gemb);
    __half* wt;
    cudaGetSymbolAddress((void**)&wt, g_wT);

    // ---- merged weight prepass ----
    // grid.x = 1152 blocks * 256 thr = 294912 >= max Np*Kp (W_d2: 384*768 = 294912).
    // (Previous rounds used 768 -> D2 tail unwritten -> the 0.1427 failures.)
    PA10 p;
    p.a[0] = {W_dna, DNA_, F_,    768, 256, OFF_DNA};
    p.a[1] = {W_img, IMG_, F_,    512, 256, OFF_IMG};
    p.a[2] = {W_qkv, F_,   QKV3_, 256, 768, OFF_QKV};
    p.a[3] = {W_o,   F_,   F_,    256, 256, OFF_O};
    p.a[4] = {W_f1,  F_,   F_,    256, 256, OFF_F1};
    p.a[5] = {W_f2,  F_,   F_,    256, 256, OFF_F2};
    p.a[6] = {W_d1,  F_,   DH_,   256, 768, OFF_D1};
    p.a[7] = {W_d2,  DH_,  GEN_,  768, 384, OFF_D2};
    p.a[8] = {W_fp,  F_,   RED_,  256, 128, OFF_FP};
    p.a[9] = {W_ge,  GEN_, GEMB_, 384, 128, OFF_GE};
    prep_all_k<<<dim3(1152, 10), 256>>>(p, wt);

    // ---- forward ----
    hgemm(dna, DNA_, wt + OFF_DNA, 768, b_dna, seqproj,      2 * F_, B_, F_, DNA_, 0);
    hgemm(img, IMG_, wt + OFF_IMG, 512, b_img, seqproj + F_, 2 * F_, B_, F_, IMG_, 0);
    hgemm(seqproj, F_, wt + OFF_QKV, 256, b_qkv, qkv, QKV3_, 2L * B_, QKV3_, F_, 0);
    attn_k<<<(B_ * 4) / 8, 256>>>(qkv, ctx);
    hgemm(ctx, F_, wt + OFF_O,  256, b_o,  t1,    F_, B_, F_, F_, 0);
    hgemm(t1,  F_, wt + OFF_F1, 256, b_f1, t2,    F_, B_, F_, F_, 1);
    hgemm(t2,  F_, wt + OFF_F2, 256, b_f2, o_fus, F_, B_, F_, F_, 0);
    hgemm(o_fus, F_, wt + OFF_D1, 256, b_d1, h,   DH_,  B_, DH_,  F_,  2);
    hgemm(h, DH_,    wt + OFF_D2, 768, b_d2, glp, GEN_, B_, GEN_, DH_, 0);
    softmax372_k<<<B_ / 8, 256>>>(glp, o_gen);
    hgemm(o_fus, F_,  wt + OFF_FP, 256, b_fp, o_red, RED_,  B_, RED_,  F_,  0);
    hgemm(o_gen, GEN_, wt + OFF_GE, 384, b_ge, gemb, GEMB_, B_, GEMB_, GEN_, 0);
    spec_head_k<<<1024, 256>>>(gemb, o_red, W_s1, b_s1, W_s2, b_s2, o_loc);
    flatten_k<<<B_, 256>>>(o_gen, o_loc, sg, sl, o_sp);
}